// round 13
// baseline (speedup 1.0000x reference)
#include <cuda_runtime.h>

// Problem constants (LinearDiffusion_2860448219950)
#define NN   8192
#define HH   4
#define EE   131072
#define DD   64
#define WW   96                 // ELL width (max degree ~58 for Poisson(32) over 8192 rows)
#define TBL  (1 << 19)
#define TBLM (TBL - 1)

// ---------------- device scratch (no allocations allowed) ----------------
// Packed hash entry: high32 = key+1 (nonzero), low32 = prio. Empty slot = 0.
__device__ unsigned long long g_tbl[TBL];       // 4 MB
__device__ int          g_slot[2 * EE];         // slot each entry landed in
__device__ int          g_deg[NN];
__device__ float        g_rowsum[NN * HH];      // per-(row,head) sum of winner e
__device__ int          g_cols[NN * WW];        // ELL columns
__device__ float4       g_evals[NN * WW];       // ELL unnormalized e-quads
__device__ float        g_x[2][NN * DD];        // ping-pong SpMM buffers

__device__ __forceinline__ unsigned int hash_key(unsigned int key) {
    return (key * 2654435761u) >> 13;  // 19-bit hash
}

// Insert key with priority prio; returns final slot. Keeps max prio per key.
// Slot transitions are monotone (0 -> (key,p) -> (key,p'>p)); no ABA.
__device__ __forceinline__ int ht_insert(unsigned int key, unsigned int prio) {
    unsigned long long desired = ((unsigned long long)(key + 1u) << 32) | prio;
    unsigned int s = hash_key(key) & TBLM;
    while (true) {
        unsigned long long cur = g_tbl[s];
        if (cur == 0ULL) {
            unsigned long long old = atomicCAS(&g_tbl[s], 0ULL, desired);
            if (old == 0ULL) return (int)s;
            cur = old;
        }
        if ((unsigned int)(cur >> 32) == key + 1u) {
            while ((unsigned int)cur < prio) {
                unsigned long long old = atomicCAS(&g_tbl[s], cur, desired);
                if (old == cur) break;
                cur = old;
            }
            return (int)s;
        }
        s = (s + 1) & TBLM;
    }
}

// ---------------- 1: hash insert, one entry per thread ----------------
// t < EE: pass-0 entry (src[k],dst[k]) prio=k+1.
// t >= EE: pass-1 entry (dst[k],src[k]) prio=(1<<17)+k+1 (applied after => higher prio).
__global__ void k_insert(const int* __restrict__ src, const int* __restrict__ dst) {
    int t = blockIdx.x * blockDim.x + threadIdx.x;
    if (t >= 2 * EE) return;
    int pass = (t >= EE);
    int k = t - (pass ? EE : 0);
    int a = src[k], b = dst[k];
    int i = pass ? b : a;
    int j = pass ? a : b;
    unsigned int key  = ((unsigned int)i << 13) | (unsigned int)j;
    unsigned int prio = (((unsigned int)pass << 17)) + (unsigned int)k + 1u;
    g_slot[t] = ht_insert(key, prio);
}

// ---------------- 2: winners -> ELL + degree + rowsum ----------------
__global__ void k_winner(const int* __restrict__ src, const int* __restrict__ dst,
                         const float* __restrict__ e) {
    int t = blockIdx.x * blockDim.x + threadIdx.x;
    if (t >= 2 * EE) return;
    int pass = (t >= EE);
    int k = t - (pass ? EE : 0);
    unsigned int prio = (((unsigned int)pass << 17)) + (unsigned int)k + 1u;
    unsigned long long entry = g_tbl[g_slot[t]];
    if ((unsigned int)entry != prio) return;   // not the last write for this (i,j)
    int a = src[k], b = dst[k];
    int i = pass ? b : a;
    int j = pass ? a : b;
    float4 ev;
    ev.x = e[0 * EE + k]; ev.y = e[1 * EE + k];
    ev.z = e[2 * EE + k]; ev.w = e[3 * EE + k];
    int pos = atomicAdd(&g_deg[i], 1);
    if (pos < WW) {
        g_cols[i * WW + pos]  = j;
        g_evals[i * WW + pos] = ev;
    }
    atomicAdd(&g_rowsum[i * HH + 0], ev.x);
    atomicAdd(&g_rowsum[i * HH + 1], ev.y);
    atomicAdd(&g_rowsum[i * HH + 2], ev.z);
    atomicAdd(&g_rowsum[i * HH + 3], ev.w);
}

// ---------------- 3: SpMM  xi = (A_unnorm @ xin) / rowsum ; res (+)= xi * invf ----------------
// (H, N, 16)-flat state layout == flat h/out (reference uses raw reshape).
// 32 threads per row: lane = 16*sub + c; sub in {0,1} processes one contiguous
// half of the row's edges (~16 -> two unroll-8 batches with a 64-reg budget so
// all 8 float4 gathers are genuinely in flight); c: head = c>>2, quad q = c&3.
// Warp-local reduction only (shfl_xor 16); no smem, no block barrier.
template <bool FIRST>
__global__ void __launch_bounds__(256, 4)
k_spmm(const float4* __restrict__ xin4, float4* __restrict__ xout4,
       float4* __restrict__ res4, float invf) {
    int tid = threadIdx.x;
    int row = blockIdx.x * 8 + (tid >> 5);
    int lane = tid & 31;
    int sub = lane >> 4;
    int c = lane & 15;
    int head = c >> 2;
    int q = c & 3;
    int hb4 = head << 15;                 // head * N * 16 / 4
    int deg = g_deg[row];
    int half = (deg + 1) >> 1;
    int rbeg = sub * half;
    int rend = sub ? deg : half;
    const float* vals = (const float*)g_evals;
    int base = row * WW;
    float4 acc = make_float4(0.f, 0.f, 0.f, 0.f);
    int r = rbeg;
#pragma unroll 1
    for (; r + 8 <= rend; r += 8) {
        int j[8]; float v[8]; float4 x[8];
#pragma unroll
        for (int u = 0; u < 8; u++) {
            j[u] = g_cols[base + r + u];
            v[u] = vals[(base + r + u) * 4 + head];
        }
#pragma unroll
        for (int u = 0; u < 8; u++)
            x[u] = __ldg(&xin4[hb4 + (j[u] << 2) + q]);
#pragma unroll
        for (int u = 0; u < 8; u++) {
            acc.x += v[u] * x[u].x; acc.y += v[u] * x[u].y;
            acc.z += v[u] * x[u].z; acc.w += v[u] * x[u].w;
        }
    }
    if (r + 4 <= rend) {
        int j[4]; float v[4]; float4 x[4];
#pragma unroll
        for (int u = 0; u < 4; u++) {
            j[u] = g_cols[base + r + u];
            v[u] = vals[(base + r + u) * 4 + head];
        }
#pragma unroll
        for (int u = 0; u < 4; u++)
            x[u] = __ldg(&xin4[hb4 + (j[u] << 2) + q]);
#pragma unroll
        for (int u = 0; u < 4; u++) {
            acc.x += v[u] * x[u].x; acc.y += v[u] * x[u].y;
            acc.z += v[u] * x[u].z; acc.w += v[u] * x[u].w;
        }
        r += 4;
    }
    for (; r < rend; r++) {
        int j = g_cols[base + r];
        float v = vals[(base + r) * 4 + head];
        float4 x = __ldg(&xin4[hb4 + (j << 2) + q]);
        acc.x += v * x.x; acc.y += v * x.y; acc.z += v * x.z; acc.w += v * x.w;
    }
    // combine the two edge-halves (lane <-> lane^16), warp-local
    acc.x += __shfl_xor_sync(0xFFFFFFFFu, acc.x, 16);
    acc.y += __shfl_xor_sync(0xFFFFFFFFu, acc.y, 16);
    acc.z += __shfl_xor_sync(0xFFFFFFFFu, acc.z, 16);
    acc.w += __shfl_xor_sync(0xFFFFFFFFu, acc.w, 16);
    if (sub == 0) {
        float rinv = 1.0f / g_rowsum[row * HH + head];
        float4 xi = make_float4(acc.x * rinv, acc.y * rinv, acc.z * rinv, acc.w * rinv);
        int o = hb4 + (row << 2) + q;
        xout4[o] = xi;
        if (FIRST) {
            float4 hv = __ldg(&xin4[o]);  // xin is h on the first hop
            res4[o] = make_float4(hv.x + xi.x, hv.y + xi.y, hv.z + xi.z, hv.w + xi.w);
        } else {
            float4 rv = res4[o];
            res4[o] = make_float4(rv.x + xi.x * invf, rv.y + xi.y * invf,
                                  rv.z + xi.z * invf, rv.w + xi.w * invf);
        }
    }
}

// ---------------- launch ----------------
extern "C" void kernel_launch(void* const* d_in, const int* in_sizes, int n_in,
                              void* d_out, int out_size) {
    const float* h   = (const float*)d_in[0];
    const float* e   = (const float*)d_in[1];
    const int*   src = (const int*)d_in[2];
    const int*   dst = (const int*)d_in[3];
    float4* out4 = (float4*)d_out;

    // zero scratch via memset nodes (graph-capturable, engine-rate)
    void* p;
    cudaGetSymbolAddress(&p, g_tbl);
    cudaMemsetAsync(p, 0, TBL * sizeof(unsigned long long));
    cudaGetSymbolAddress(&p, g_deg);
    cudaMemsetAsync(p, 0, NN * sizeof(int));
    cudaGetSymbolAddress(&p, g_rowsum);
    cudaMemsetAsync(p, 0, NN * HH * sizeof(float));

    k_insert<<<(2 * EE + 255) / 256, 256>>>(src, dst);
    k_winner<<<(2 * EE + 255) / 256, 256>>>(src, dst, e);

    float* xa;  float* xb;
    cudaGetSymbolAddress((void**)&xa, g_x);
    xb = xa + NN * DD;

    const float invf[6] = {1.0f, 0.5f, 1.0f / 6.0f, 1.0f / 24.0f, 1.0f / 120.0f, 1.0f / 720.0f};
    // Hop 1: h -> xa, fused res = h + x1
    k_spmm<true><<<NN / 8, 256>>>((const float4*)h, (float4*)xa, out4, invf[0]);
    const float* cur = xa;
    float* bufs[2] = {xa, xb};            // it=1 -> xb, it=2 -> xa, alternating vs cur
    for (int it = 1; it < 6; it++) {
        float* nxt = bufs[it & 1];
        k_spmm<false><<<NN / 8, 256>>>((const float4*)cur, (float4*)nxt, out4, invf[it]);
        cur = nxt;
    }
}

// round 14
// speedup vs baseline: 1.0419x; 1.0419x over previous
#include <cuda_runtime.h>
#include <cuda_bf16.h>

// Problem constants (LinearDiffusion_2860448219950)
#define NN   8192
#define HH   4
#define EE   131072
#define DD   64
#define WW   96                 // ELL width (max degree ~58 for Poisson(32) over 8192 rows)
#define TBL  (1 << 19)
#define TBLM (TBL - 1)

// ---------------- device scratch (no allocations allowed) ----------------
__device__ unsigned long long g_tbl[TBL];       // packed hash: hi32=key+1, lo32=prio
__device__ int          g_slot[2 * EE];
__device__ int          g_deg[NN];
__device__ float        g_rowsum[NN * HH];
__device__ int          g_cols[NN * WW];
__device__ float4       g_evals[NN * WW];       // unnormalized e-quads (fp32)
__device__ __nv_bfloat16 g_xb[2][NN * DD];      // ping-pong bf16 x buffers (1 MB each)

__device__ __forceinline__ unsigned int hash_key(unsigned int key) {
    return (key * 2654435761u) >> 13;
}

__device__ __forceinline__ int ht_insert(unsigned int key, unsigned int prio) {
    unsigned long long desired = ((unsigned long long)(key + 1u) << 32) | prio;
    unsigned int s = hash_key(key) & TBLM;
    while (true) {
        unsigned long long cur = g_tbl[s];
        if (cur == 0ULL) {
            unsigned long long old = atomicCAS(&g_tbl[s], 0ULL, desired);
            if (old == 0ULL) return (int)s;
            cur = old;
        }
        if ((unsigned int)(cur >> 32) == key + 1u) {
            while ((unsigned int)cur < prio) {
                unsigned long long old = atomicCAS(&g_tbl[s], cur, desired);
                if (old == cur) break;
                cur = old;
            }
            return (int)s;
        }
        s = (s + 1) & TBLM;
    }
}

// ---------------- 1: hash insert ----------------
__global__ void k_insert(const int* __restrict__ src, const int* __restrict__ dst) {
    int t = blockIdx.x * blockDim.x + threadIdx.x;
    if (t >= 2 * EE) return;
    int pass = (t >= EE);
    int k = t - (pass ? EE : 0);
    int a = src[k], b = dst[k];
    int i = pass ? b : a;
    int j = pass ? a : b;
    unsigned int key  = ((unsigned int)i << 13) | (unsigned int)j;
    unsigned int prio = (((unsigned int)pass << 17)) + (unsigned int)k + 1u;
    g_slot[t] = ht_insert(key, prio);
}

// ---------------- 2: winners -> ELL + degree + rowsum ----------------
__global__ void k_winner(const int* __restrict__ src, const int* __restrict__ dst,
                         const float* __restrict__ e) {
    int t = blockIdx.x * blockDim.x + threadIdx.x;
    if (t >= 2 * EE) return;
    int pass = (t >= EE);
    int k = t - (pass ? EE : 0);
    unsigned int prio = (((unsigned int)pass << 17)) + (unsigned int)k + 1u;
    unsigned long long entry = g_tbl[g_slot[t]];
    if ((unsigned int)entry != prio) return;
    int a = src[k], b = dst[k];
    int i = pass ? b : a;
    int j = pass ? a : b;
    float4 ev;
    ev.x = e[0 * EE + k]; ev.y = e[1 * EE + k];
    ev.z = e[2 * EE + k]; ev.w = e[3 * EE + k];
    int pos = atomicAdd(&g_deg[i], 1);
    if (pos < WW) {
        g_cols[i * WW + pos]  = j;
        g_evals[i * WW + pos] = ev;
    }
    atomicAdd(&g_rowsum[i * HH + 0], ev.x);
    atomicAdd(&g_rowsum[i * HH + 1], ev.y);
    atomicAdd(&g_rowsum[i * HH + 2], ev.z);
    atomicAdd(&g_rowsum[i * HH + 3], ev.w);
}

// Common thread-geometry: 32 threads/row, lane = 16*sub + c; sub in {0,1} takes
// one contiguous half of the row's edges; c: head = c>>2, quad q = c&3.
// (H,N,16)-flat state layout == flat h/out (reference uses raw reshape).

// ---------------- 3a: hop 1 — fp32 gather of h; write bf16 x1; res = h + x1 ----------------
__global__ void k_spmm_first(const float4* __restrict__ xin4, uint2* __restrict__ xoutb,
                             float4* __restrict__ res4) {
    int tid = threadIdx.x;
    int row = blockIdx.x * 8 + (tid >> 5);
    int lane = tid & 31;
    int sub = lane >> 4;
    int c = lane & 15;
    int head = c >> 2;
    int q = c & 3;
    int hb4 = head << 15;                 // head * N * 4 (float4 units)
    int deg = g_deg[row];
    int half = (deg + 1) >> 1;
    int rbeg = sub * half;
    int rend = sub ? deg : half;
    const float* vals = (const float*)g_evals;
    int base = row * WW;
    float4 acc = make_float4(0.f, 0.f, 0.f, 0.f);
    int r = rbeg;
#pragma unroll 1
    for (; r + 4 <= rend; r += 4) {
        int j0 = g_cols[base + r],     j1 = g_cols[base + r + 1];
        int j2 = g_cols[base + r + 2], j3 = g_cols[base + r + 3];
        float v0 = vals[(base + r) * 4 + head];
        float v1 = vals[(base + r + 1) * 4 + head];
        float v2 = vals[(base + r + 2) * 4 + head];
        float v3 = vals[(base + r + 3) * 4 + head];
        float4 x0 = __ldg(&xin4[hb4 + (j0 << 2) + q]);
        float4 x1 = __ldg(&xin4[hb4 + (j1 << 2) + q]);
        float4 x2 = __ldg(&xin4[hb4 + (j2 << 2) + q]);
        float4 x3 = __ldg(&xin4[hb4 + (j3 << 2) + q]);
        acc.x += v0 * x0.x + v1 * x1.x + v2 * x2.x + v3 * x3.x;
        acc.y += v0 * x0.y + v1 * x1.y + v2 * x2.y + v3 * x3.y;
        acc.z += v0 * x0.z + v1 * x1.z + v2 * x2.z + v3 * x3.z;
        acc.w += v0 * x0.w + v1 * x1.w + v2 * x2.w + v3 * x3.w;
    }
    for (; r < rend; r++) {
        int j = g_cols[base + r];
        float v = vals[(base + r) * 4 + head];
        float4 x = __ldg(&xin4[hb4 + (j << 2) + q]);
        acc.x += v * x.x; acc.y += v * x.y; acc.z += v * x.z; acc.w += v * x.w;
    }
    acc.x += __shfl_xor_sync(0xFFFFFFFFu, acc.x, 16);
    acc.y += __shfl_xor_sync(0xFFFFFFFFu, acc.y, 16);
    acc.z += __shfl_xor_sync(0xFFFFFFFFu, acc.z, 16);
    acc.w += __shfl_xor_sync(0xFFFFFFFFu, acc.w, 16);
    if (sub == 0) {
        float rinv = 1.0f / g_rowsum[row * HH + head];
        float4 xi = make_float4(acc.x * rinv, acc.y * rinv, acc.z * rinv, acc.w * rinv);
        int o = hb4 + (row << 2) + q;     // float4/uint2 index coincide (both quads)
        __nv_bfloat162 b0 = __floats2bfloat162_rn(xi.x, xi.y);
        __nv_bfloat162 b1 = __floats2bfloat162_rn(xi.z, xi.w);
        uint2 w;
        w.x = *reinterpret_cast<unsigned int*>(&b0);
        w.y = *reinterpret_cast<unsigned int*>(&b1);
        xoutb[o] = w;
        float4 hv = __ldg(&xin4[o]);
        res4[o] = make_float4(hv.x + xi.x, hv.y + xi.y, hv.z + xi.z, hv.w + xi.w);
    }
}

// ---------------- 3b: hops 2-6 — bf16 gather (8 B/lane); res += xi * invf ----------------
__global__ void k_spmm_b(const uint2* __restrict__ xinb, uint2* __restrict__ xoutb,
                         float4* __restrict__ res4, float invf) {
    int tid = threadIdx.x;
    int row = blockIdx.x * 8 + (tid >> 5);
    int lane = tid & 31;
    int sub = lane >> 4;
    int c = lane & 15;
    int head = c >> 2;
    int q = c & 3;
    int hb4 = head << 15;                 // head * N * 4 (uint2 quads)
    int deg = g_deg[row];
    int half = (deg + 1) >> 1;
    int rbeg = sub * half;
    int rend = sub ? deg : half;
    const float* vals = (const float*)g_evals;
    int base = row * WW;
    float4 acc = make_float4(0.f, 0.f, 0.f, 0.f);
    int r = rbeg;
#pragma unroll 1
    for (; r + 8 <= rend; r += 8) {
        int j[8]; float v[8]; uint2 w[8];
#pragma unroll
        for (int u = 0; u < 8; u++) {
            j[u] = g_cols[base + r + u];
            v[u] = vals[(base + r + u) * 4 + head];
        }
#pragma unroll
        for (int u = 0; u < 8; u++)
            w[u] = __ldg(&xinb[hb4 + (j[u] << 2) + q]);
#pragma unroll
        for (int u = 0; u < 8; u++) {
            float2 lo = __bfloat1622float2(*reinterpret_cast<__nv_bfloat162*>(&w[u].x));
            float2 hi = __bfloat1622float2(*reinterpret_cast<__nv_bfloat162*>(&w[u].y));
            acc.x += v[u] * lo.x; acc.y += v[u] * lo.y;
            acc.z += v[u] * hi.x; acc.w += v[u] * hi.y;
        }
    }
    if (r + 4 <= rend) {
        int j[4]; float v[4]; uint2 w[4];
#pragma unroll
        for (int u = 0; u < 4; u++) {
            j[u] = g_cols[base + r + u];
            v[u] = vals[(base + r + u) * 4 + head];
        }
#pragma unroll
        for (int u = 0; u < 4; u++)
            w[u] = __ldg(&xinb[hb4 + (j[u] << 2) + q]);
#pragma unroll
        for (int u = 0; u < 4; u++) {
            float2 lo = __bfloat1622float2(*reinterpret_cast<__nv_bfloat162*>(&w[u].x));
            float2 hi = __bfloat1622float2(*reinterpret_cast<__nv_bfloat162*>(&w[u].y));
            acc.x += v[u] * lo.x; acc.y += v[u] * lo.y;
            acc.z += v[u] * hi.x; acc.w += v[u] * hi.y;
        }
        r += 4;
    }
    for (; r < rend; r++) {
        int jj = g_cols[base + r];
        float v = vals[(base + r) * 4 + head];
        uint2 w = __ldg(&xinb[hb4 + (jj << 2) + q]);
        float2 lo = __bfloat1622float2(*reinterpret_cast<__nv_bfloat162*>(&w.x));
        float2 hi = __bfloat1622float2(*reinterpret_cast<__nv_bfloat162*>(&w.y));
        acc.x += v * lo.x; acc.y += v * lo.y;
        acc.z += v * hi.x; acc.w += v * hi.y;
    }
    acc.x += __shfl_xor_sync(0xFFFFFFFFu, acc.x, 16);
    acc.y += __shfl_xor_sync(0xFFFFFFFFu, acc.y, 16);
    acc.z += __shfl_xor_sync(0xFFFFFFFFu, acc.z, 16);
    acc.w += __shfl_xor_sync(0xFFFFFFFFu, acc.w, 16);
    if (sub == 0) {
        float rinv = 1.0f / g_rowsum[row * HH + head];
        float4 xi = make_float4(acc.x * rinv, acc.y * rinv, acc.z * rinv, acc.w * rinv);
        int o = hb4 + (row << 2) + q;
        __nv_bfloat162 b0 = __floats2bfloat162_rn(xi.x, xi.y);
        __nv_bfloat162 b1 = __floats2bfloat162_rn(xi.z, xi.w);
        uint2 w;
        w.x = *reinterpret_cast<unsigned int*>(&b0);
        w.y = *reinterpret_cast<unsigned int*>(&b1);
        xoutb[o] = w;
        float4 rv = res4[o];
        res4[o] = make_float4(rv.x + xi.x * invf, rv.y + xi.y * invf,
                              rv.z + xi.z * invf, rv.w + xi.w * invf);
    }
}

// ---------------- launch ----------------
extern "C" void kernel_launch(void* const* d_in, const int* in_sizes, int n_in,
                              void* d_out, int out_size) {
    const float* h   = (const float*)d_in[0];
    const float* e   = (const float*)d_in[1];
    const int*   src = (const int*)d_in[2];
    const int*   dst = (const int*)d_in[3];
    float4* out4 = (float4*)d_out;

    // zero scratch via memset nodes (graph-capturable, engine-rate)
    void* p;
    cudaGetSymbolAddress(&p, g_tbl);
    cudaMemsetAsync(p, 0, TBL * sizeof(unsigned long long));
    cudaGetSymbolAddress(&p, g_deg);
    cudaMemsetAsync(p, 0, NN * sizeof(int));
    cudaGetSymbolAddress(&p, g_rowsum);
    cudaMemsetAsync(p, 0, NN * HH * sizeof(float));

    k_insert<<<(2 * EE + 255) / 256, 256>>>(src, dst);
    k_winner<<<(2 * EE + 255) / 256, 256>>>(src, dst, e);

    __nv_bfloat16* xa;
    cudaGetSymbolAddress((void**)&xa, g_xb);
    __nv_bfloat16* xb = xa + NN * DD;

    const float invf[6] = {1.0f, 0.5f, 1.0f / 6.0f, 1.0f / 24.0f, 1.0f / 120.0f, 1.0f / 720.0f};
    // Hop 1: fp32 gather of h -> bf16 xa, fused res = h + x1
    k_spmm_first<<<NN / 8, 256>>>((const float4*)h, (uint2*)xa, out4);
    const __nv_bfloat16* cur = xa;
    __nv_bfloat16* bufs[2] = {xa, xb};    // it=1 -> xb, it=2 -> xa, alternating vs cur
    for (int it = 1; it < 6; it++) {
        __nv_bfloat16* nxt = bufs[it & 1];
        k_spmm_b<<<NN / 8, 256>>>((const uint2*)cur, (uint2*)nxt, out4, invf[it]);
        cur = nxt;
    }
}

// round 15
// speedup vs baseline: 1.1489x; 1.1027x over previous
#include <cuda_runtime.h>
#include <cuda_bf16.h>

// Problem constants (LinearDiffusion_2860448219950)
#define NN   8192
#define HH   4
#define EE   131072
#define DD   64
#define WW   96                 // ELL width (max degree ~58 for Poisson(32) over 8192 rows)
#define TBL  (1 << 19)
#define TBLM (TBL - 1)

// ---------------- device scratch (no allocations allowed) ----------------
__device__ unsigned long long g_tbl[TBL];       // packed hash: hi32=key+1, lo32=prio
__device__ int          g_slot[2 * EE];
__device__ int          g_deg[NN];
__device__ float        g_rowsum[NN * HH];
__device__ int          g_cols[NN * WW];
__device__ float4       g_evals[NN * WW];       // unnormalized e-quads (fp32)
__device__ __nv_bfloat16 g_xb[2][NN * DD];      // ping-pong bf16 x buffers, ROW-MAJOR (N,64)

__device__ __forceinline__ unsigned int hash_key(unsigned int key) {
    return (key * 2654435761u) >> 13;
}

__device__ __forceinline__ int ht_insert(unsigned int key, unsigned int prio) {
    unsigned long long desired = ((unsigned long long)(key + 1u) << 32) | prio;
    unsigned int s = hash_key(key) & TBLM;
    while (true) {
        unsigned long long cur = g_tbl[s];
        if (cur == 0ULL) {
            unsigned long long old = atomicCAS(&g_tbl[s], 0ULL, desired);
            if (old == 0ULL) return (int)s;
            cur = old;
        }
        if ((unsigned int)(cur >> 32) == key + 1u) {
            while ((unsigned int)cur < prio) {
                unsigned long long old = atomicCAS(&g_tbl[s], cur, desired);
                if (old == cur) break;
                cur = old;
            }
            return (int)s;
        }
        s = (s + 1) & TBLM;
    }
}

// ---------------- 1: hash insert ----------------
__global__ void k_insert(const int* __restrict__ src, const int* __restrict__ dst) {
    int t = blockIdx.x * blockDim.x + threadIdx.x;
    if (t >= 2 * EE) return;
    int pass = (t >= EE);
    int k = t - (pass ? EE : 0);
    int a = src[k], b = dst[k];
    int i = pass ? b : a;
    int j = pass ? a : b;
    unsigned int key  = ((unsigned int)i << 13) | (unsigned int)j;
    unsigned int prio = (((unsigned int)pass << 17)) + (unsigned int)k + 1u;
    g_slot[t] = ht_insert(key, prio);
}

// ---------------- 2: winners -> ELL + degree + rowsum ----------------
__global__ void k_winner(const int* __restrict__ src, const int* __restrict__ dst,
                         const float* __restrict__ e) {
    int t = blockIdx.x * blockDim.x + threadIdx.x;
    if (t >= 2 * EE) return;
    int pass = (t >= EE);
    int k = t - (pass ? EE : 0);
    unsigned int prio = (((unsigned int)pass << 17)) + (unsigned int)k + 1u;
    unsigned long long entry = g_tbl[g_slot[t]];
    if ((unsigned int)entry != prio) return;
    int a = src[k], b = dst[k];
    int i = pass ? b : a;
    int j = pass ? a : b;
    float4 ev;
    ev.x = e[0 * EE + k]; ev.y = e[1 * EE + k];
    ev.z = e[2 * EE + k]; ev.w = e[3 * EE + k];
    int pos = atomicAdd(&g_deg[i], 1);
    if (pos < WW) {
        g_cols[i * WW + pos]  = j;
        g_evals[i * WW + pos] = ev;
    }
    atomicAdd(&g_rowsum[i * HH + 0], ev.x);
    atomicAdd(&g_rowsum[i * HH + 1], ev.y);
    atomicAdd(&g_rowsum[i * HH + 2], ev.z);
    atomicAdd(&g_rowsum[i * HH + 3], ev.w);
}

// Thread geometry (both spmm kernels): 32 threads/row, lane = 16*sub + c;
// sub in {0,1} takes one contiguous half of the row's edges;
// c = head*4 + q (head = c>>2, q = c&3).
// x buffers: bf16 ROW-MAJOR (N, 64) -> row = 16 uint2, a sub's 16 lanes read one
// 128B line per gathered row (4x fewer L1TEX wavefronts than (H,N,16) layout).
// h and res keep the fixed (H,N,16)-flat fp32 layout of the harness.

// ---------------- 3a: hop 1 — fp32 gather of h; write bf16 x1 row-major; res = h + x1 ----------------
__global__ void k_spmm_first(const float4* __restrict__ xin4, uint2* __restrict__ xoutb,
                             float4* __restrict__ res4) {
    int tid = threadIdx.x;
    int row = blockIdx.x * 8 + (tid >> 5);
    int lane = tid & 31;
    int sub = lane >> 4;
    int c = lane & 15;
    int head = c >> 2;
    int q = c & 3;
    int hb4 = head << 15;                 // head * N * 4 (float4 units, h layout)
    int deg = g_deg[row];
    int half = (deg + 1) >> 1;
    int rbeg = sub * half;
    int rend = sub ? deg : half;
    const float* vals = (const float*)g_evals;
    int base = row * WW;
    float4 acc = make_float4(0.f, 0.f, 0.f, 0.f);
    int r = rbeg;
#pragma unroll 1
    for (; r + 4 <= rend; r += 4) {
        int j0 = g_cols[base + r],     j1 = g_cols[base + r + 1];
        int j2 = g_cols[base + r + 2], j3 = g_cols[base + r + 3];
        float v0 = vals[(base + r) * 4 + head];
        float v1 = vals[(base + r + 1) * 4 + head];
        float v2 = vals[(base + r + 2) * 4 + head];
        float v3 = vals[(base + r + 3) * 4 + head];
        float4 x0 = __ldg(&xin4[hb4 + (j0 << 2) + q]);
        float4 x1 = __ldg(&xin4[hb4 + (j1 << 2) + q]);
        float4 x2 = __ldg(&xin4[hb4 + (j2 << 2) + q]);
        float4 x3 = __ldg(&xin4[hb4 + (j3 << 2) + q]);
        acc.x += v0 * x0.x + v1 * x1.x + v2 * x2.x + v3 * x3.x;
        acc.y += v0 * x0.y + v1 * x1.y + v2 * x2.y + v3 * x3.y;
        acc.z += v0 * x0.z + v1 * x1.z + v2 * x2.z + v3 * x3.z;
        acc.w += v0 * x0.w + v1 * x1.w + v2 * x2.w + v3 * x3.w;
    }
    for (; r < rend; r++) {
        int j = g_cols[base + r];
        float v = vals[(base + r) * 4 + head];
        float4 x = __ldg(&xin4[hb4 + (j << 2) + q]);
        acc.x += v * x.x; acc.y += v * x.y; acc.z += v * x.z; acc.w += v * x.w;
    }
    acc.x += __shfl_xor_sync(0xFFFFFFFFu, acc.x, 16);
    acc.y += __shfl_xor_sync(0xFFFFFFFFu, acc.y, 16);
    acc.z += __shfl_xor_sync(0xFFFFFFFFu, acc.z, 16);
    acc.w += __shfl_xor_sync(0xFFFFFFFFu, acc.w, 16);
    if (sub == 0) {
        float rinv = 1.0f / g_rowsum[row * HH + head];
        float4 xi = make_float4(acc.x * rinv, acc.y * rinv, acc.z * rinv, acc.w * rinv);
        // bf16 x1 write, row-major: row = 16 uint2, element c
        __nv_bfloat162 b0 = __floats2bfloat162_rn(xi.x, xi.y);
        __nv_bfloat162 b1 = __floats2bfloat162_rn(xi.z, xi.w);
        uint2 w;
        w.x = *reinterpret_cast<unsigned int*>(&b0);
        w.y = *reinterpret_cast<unsigned int*>(&b1);
        xoutb[(row << 4) + c] = w;
        // res in fixed (H,N,16) layout
        int o = hb4 + (row << 2) + q;
        float4 hv = __ldg(&xin4[o]);
        res4[o] = make_float4(hv.x + xi.x, hv.y + xi.y, hv.z + xi.z, hv.w + xi.w);
    }
}

// ---------------- 3b: hops 2-6 — row-major bf16 gather (one 128B line per row); res += xi*invf ----------------
__global__ void k_spmm_b(const uint2* __restrict__ xinb, uint2* __restrict__ xoutb,
                         float4* __restrict__ res4, float invf) {
    int tid = threadIdx.x;
    int row = blockIdx.x * 8 + (tid >> 5);
    int lane = tid & 31;
    int sub = lane >> 4;
    int c = lane & 15;
    int head = c >> 2;
    int q = c & 3;
    int deg = g_deg[row];
    int half = (deg + 1) >> 1;
    int rbeg = sub * half;
    int rend = sub ? deg : half;
    const float* vals = (const float*)g_evals;
    int base = row * WW;
    float4 acc = make_float4(0.f, 0.f, 0.f, 0.f);
    int r = rbeg;
#pragma unroll 1
    for (; r + 8 <= rend; r += 8) {
        int j[8]; float v[8]; uint2 w[8];
#pragma unroll
        for (int u = 0; u < 8; u++) {
            j[u] = g_cols[base + r + u];
            v[u] = vals[(base + r + u) * 4 + head];
        }
#pragma unroll
        for (int u = 0; u < 8; u++)
            w[u] = __ldg(&xinb[(j[u] << 4) + c]);
#pragma unroll
        for (int u = 0; u < 8; u++) {
            float2 lo = __bfloat1622float2(*reinterpret_cast<__nv_bfloat162*>(&w[u].x));
            float2 hi = __bfloat1622float2(*reinterpret_cast<__nv_bfloat162*>(&w[u].y));
            acc.x += v[u] * lo.x; acc.y += v[u] * lo.y;
            acc.z += v[u] * hi.x; acc.w += v[u] * hi.y;
        }
    }
    if (r + 4 <= rend) {
        int j[4]; float v[4]; uint2 w[4];
#pragma unroll
        for (int u = 0; u < 4; u++) {
            j[u] = g_cols[base + r + u];
            v[u] = vals[(base + r + u) * 4 + head];
        }
#pragma unroll
        for (int u = 0; u < 4; u++)
            w[u] = __ldg(&xinb[(j[u] << 4) + c]);
#pragma unroll
        for (int u = 0; u < 4; u++) {
            float2 lo = __bfloat1622float2(*reinterpret_cast<__nv_bfloat162*>(&w[u].x));
            float2 hi = __bfloat1622float2(*reinterpret_cast<__nv_bfloat162*>(&w[u].y));
            acc.x += v[u] * lo.x; acc.y += v[u] * lo.y;
            acc.z += v[u] * hi.x; acc.w += v[u] * hi.y;
        }
        r += 4;
    }
    for (; r < rend; r++) {
        int jj = g_cols[base + r];
        float v = vals[(base + r) * 4 + head];
        uint2 w = __ldg(&xinb[(jj << 4) + c]);
        float2 lo = __bfloat1622float2(*reinterpret_cast<__nv_bfloat162*>(&w.x));
        float2 hi = __bfloat1622float2(*reinterpret_cast<__nv_bfloat162*>(&w.y));
        acc.x += v * lo.x; acc.y += v * lo.y;
        acc.z += v * hi.x; acc.w += v * hi.y;
    }
    acc.x += __shfl_xor_sync(0xFFFFFFFFu, acc.x, 16);
    acc.y += __shfl_xor_sync(0xFFFFFFFFu, acc.y, 16);
    acc.z += __shfl_xor_sync(0xFFFFFFFFu, acc.z, 16);
    acc.w += __shfl_xor_sync(0xFFFFFFFFu, acc.w, 16);
    if (sub == 0) {
        float rinv = 1.0f / g_rowsum[row * HH + head];
        float4 xi = make_float4(acc.x * rinv, acc.y * rinv, acc.z * rinv, acc.w * rinv);
        __nv_bfloat162 b0 = __floats2bfloat162_rn(xi.x, xi.y);
        __nv_bfloat162 b1 = __floats2bfloat162_rn(xi.z, xi.w);
        uint2 w;
        w.x = *reinterpret_cast<unsigned int*>(&b0);
        w.y = *reinterpret_cast<unsigned int*>(&b1);
        xoutb[(row << 4) + c] = w;
        int o = (head << 15) + (row << 2) + q;   // res in fixed (H,N,16) layout
        float4 rv = res4[o];
        res4[o] = make_float4(rv.x + xi.x * invf, rv.y + xi.y * invf,
                              rv.z + xi.z * invf, rv.w + xi.w * invf);
    }
}

// ---------------- launch ----------------
extern "C" void kernel_launch(void* const* d_in, const int* in_sizes, int n_in,
                              void* d_out, int out_size) {
    const float* h   = (const float*)d_in[0];
    const float* e   = (const float*)d_in[1];
    const int*   src = (const int*)d_in[2];
    const int*   dst = (const int*)d_in[3];
    float4* out4 = (float4*)d_out;

    // zero scratch via memset nodes (graph-capturable, engine-rate)
    void* p;
    cudaGetSymbolAddress(&p, g_tbl);
    cudaMemsetAsync(p, 0, TBL * sizeof(unsigned long long));
    cudaGetSymbolAddress(&p, g_deg);
    cudaMemsetAsync(p, 0, NN * sizeof(int));
    cudaGetSymbolAddress(&p, g_rowsum);
    cudaMemsetAsync(p, 0, NN * HH * sizeof(float));

    k_insert<<<(2 * EE + 255) / 256, 256>>>(src, dst);
    k_winner<<<(2 * EE + 255) / 256, 256>>>(src, dst, e);

    __nv_bfloat16* xa;
    cudaGetSymbolAddress((void**)&xa, g_xb);
    __nv_bfloat16* xb = xa + NN * DD;

    const float invf[6] = {1.0f, 0.5f, 1.0f / 6.0f, 1.0f / 24.0f, 1.0f / 120.0f, 1.0f / 720.0f};
    // Hop 1: fp32 gather of h -> bf16 xa (row-major), fused res = h + x1
    k_spmm_first<<<NN / 8, 256>>>((const float4*)h, (uint2*)xa, out4);
    const __nv_bfloat16* cur = xa;
    __nv_bfloat16* bufs[2] = {xa, xb};    // it=1 -> xb, it=2 -> xa, alternating vs cur
    for (int it = 1; it < 6; it++) {
        __nv_bfloat16* nxt = bufs[it & 1];
        k_spmm_b<<<NN / 8, 256>>>((const uint2*)cur, (uint2*)nxt, out4, invf[it]);
        cur = nxt;
    }
}